// round 1
// baseline (speedup 1.0000x reference)
#include <cuda_runtime.h>

#define NTOK 16384
#define DIN  1024
#define DH   256
#define DOUT 1024
#define NEXP 8

// scratch (static device globals; no allocation at runtime)
__device__ int   g_count[NEXP];
__device__ int   g_tok[NEXP * NTOK];
__device__ float g_wt[NEXP * NTOK];
__device__ float g_H[(size_t)NEXP * NTOK * DH];   // 128 MiB

// ---------------------------------------------------------------------------
// Kernel 0: zero the accumulated output region + expert counters
// ---------------------------------------------------------------------------
__global__ void moe_zero_kernel(float4* __restrict__ out4, int n4) {
    int i = blockIdx.x * blockDim.x + threadIdx.x;
    if (i < NEXP) g_count[i] = 0;
    float4 z = make_float4(0.f, 0.f, 0.f, 0.f);
    for (int idx = i; idx < n4; idx += gridDim.x * blockDim.x) out4[idx] = z;
}

// ---------------------------------------------------------------------------
// Kernel 1: gating. One warp per token: 8 fp32 dot products (exact), top-2,
// softmax, scatter into per-expert lists.
// ---------------------------------------------------------------------------
__global__ void moe_gate_kernel(const float* __restrict__ x,
                                const float* __restrict__ Wg,
                                const float* __restrict__ bg,
                                float* __restrict__ gate_out,  // [N, 8]
                                int N) {
    int warp = (blockIdx.x * blockDim.x + threadIdx.x) >> 5;
    int lane = threadIdx.x & 31;
    if (warp >= N) return;

    const float* xr = x + (size_t)warp * DIN;
    float acc[8];
#pragma unroll
    for (int e = 0; e < 8; e++) acc[e] = 0.f;

    for (int k = lane; k < DIN; k += 32) {
        float xv = xr[k];
        const float4* wrow = (const float4*)(Wg + (size_t)k * 8);
        float4 w0 = wrow[0];
        float4 w1 = wrow[1];
        acc[0] += xv * w0.x; acc[1] += xv * w0.y;
        acc[2] += xv * w0.z; acc[3] += xv * w0.w;
        acc[4] += xv * w1.x; acc[5] += xv * w1.y;
        acc[6] += xv * w1.z; acc[7] += xv * w1.w;
    }
#pragma unroll
    for (int off = 16; off; off >>= 1) {
#pragma unroll
        for (int e = 0; e < 8; e++)
            acc[e] += __shfl_xor_sync(0xFFFFFFFFu, acc[e], off);
    }

    if (lane == 0) {
        float lg[8];
#pragma unroll
        for (int e = 0; e < 8; e++) {
            lg[e] = acc[e] + bg[e];
            gate_out[(size_t)warp * 8 + e] = lg[e];
        }
        // top-2 (first index wins ties, matching jax top_k)
        int i0 = 0; float m0 = lg[0];
#pragma unroll
        for (int e = 1; e < 8; e++) if (lg[e] > m0) { m0 = lg[e]; i0 = e; }
        int i1 = -1; float m1 = -1e30f;
#pragma unroll
        for (int e = 0; e < 8; e++) if (e != i0 && lg[e] > m1) { m1 = lg[e]; i1 = e; }
        float e1 = __expf(m1 - m0);
        float inv = 1.f / (1.f + e1);
        float w0 = inv;
        float w1 = e1 * inv;

        int p0 = atomicAdd(&g_count[i0], 1);
        g_tok[i0 * NTOK + p0] = warp;
        g_wt[i0 * NTOK + p0] = w0;
        int p1 = atomicAdd(&g_count[i1], 1);
        g_tok[i1 * NTOK + p1] = warp;
        g_wt[i1 * NTOK + p1] = w1;
    }
}

// ---------------------------------------------------------------------------
// Tiled fp32 GEMM params
// ---------------------------------------------------------------------------
#define BM 64
#define BN 64
#define BK 16

// Kernel 2: H = relu(X[gathered] @ W1[e] + b1[e])     (K = 1024, N-dim = 256)
__global__ void __launch_bounds__(256, 4)
moe_gemm1_kernel(const float* __restrict__ x,
                 const float* __restrict__ W1,
                 const float* __restrict__ b1) {
    int e  = blockIdx.z;
    int m0 = blockIdx.y * BM;
    int n0 = blockIdx.x * BN;
    int M  = g_count[e];
    if (m0 >= M) return;

    __shared__ float Xs[BK][BM];
    __shared__ float Ws[BK][BN];

    int tid = threadIdx.x;
    // X loads: thread -> (m, k-offset)
    int lm = tid >> 2;
    int lk = (tid & 3) * 4;
    int gm = m0 + lm;
    const float* xrow = (gm < M) ? (x + (size_t)g_tok[e * NTOK + gm] * DIN) : nullptr;
    // W loads: thread -> (k, n-offset)
    int wk = tid >> 4;
    int wn = (tid & 15) * 4;
    const float* wbase = W1 + (size_t)e * DIN * DH + n0 + wn;

    int ty = tid >> 4;   // 0..15 -> m group
    int tx = tid & 15;   // 0..15 -> n group

    float acc[4][4];
#pragma unroll
    for (int i = 0; i < 4; i++)
#pragma unroll
        for (int j = 0; j < 4; j++) acc[i][j] = 0.f;

    for (int k0 = 0; k0 < DIN; k0 += BK) {
        float4 xv = xrow ? *(const float4*)(xrow + k0 + lk)
                         : make_float4(0.f, 0.f, 0.f, 0.f);
        Xs[lk + 0][lm] = xv.x;
        Xs[lk + 1][lm] = xv.y;
        Xs[lk + 2][lm] = xv.z;
        Xs[lk + 3][lm] = xv.w;
        *(float4*)&Ws[wk][wn] = *(const float4*)(wbase + (size_t)(k0 + wk) * DH);
        __syncthreads();
#pragma unroll
        for (int k = 0; k < BK; k++) {
            float4 a = *(float4*)&Xs[k][ty * 4];
            float4 b = *(float4*)&Ws[k][tx * 4];
            acc[0][0] += a.x * b.x; acc[0][1] += a.x * b.y; acc[0][2] += a.x * b.z; acc[0][3] += a.x * b.w;
            acc[1][0] += a.y * b.x; acc[1][1] += a.y * b.y; acc[1][2] += a.y * b.z; acc[1][3] += a.y * b.w;
            acc[2][0] += a.z * b.x; acc[2][1] += a.z * b.y; acc[2][2] += a.z * b.z; acc[2][3] += a.z * b.w;
            acc[3][0] += a.w * b.x; acc[3][1] += a.w * b.y; acc[3][2] += a.w * b.z; acc[3][3] += a.w * b.w;
        }
        __syncthreads();
    }

    float4 bb = *(const float4*)(b1 + (size_t)e * DH + n0 + tx * 4);
#pragma unroll
    for (int i = 0; i < 4; i++) {
        int row = m0 + ty * 4 + i;
        if (row < M) {
            float4 h;
            h.x = fmaxf(acc[i][0] + bb.x, 0.f);
            h.y = fmaxf(acc[i][1] + bb.y, 0.f);
            h.z = fmaxf(acc[i][2] + bb.z, 0.f);
            h.w = fmaxf(acc[i][3] + bb.w, 0.f);
            *(float4*)(g_H + ((size_t)e * NTOK + row) * DH + n0 + tx * 4) = h;
        }
    }
}

// Kernel 3: Y = H @ W2[e] + b2[e]; out[tok] += w * Y  (K = 256, N-dim = 1024)
__global__ void __launch_bounds__(256, 4)
moe_gemm2_kernel(const float* __restrict__ W2,
                 const float* __restrict__ b2,
                 float* __restrict__ out) {
    int e  = blockIdx.z;
    int m0 = blockIdx.y * BM;
    int n0 = blockIdx.x * BN;
    int M  = g_count[e];
    if (m0 >= M) return;

    __shared__ float Hs[BK][BM];
    __shared__ float Ws[BK][BN];

    int tid = threadIdx.x;
    int lm = tid >> 2;
    int lk = (tid & 3) * 4;
    const float* hrow = g_H + ((size_t)e * NTOK + (m0 + lm)) * DH;   // always in-bounds capacity
    int wk = tid >> 4;
    int wn = (tid & 15) * 4;
    const float* wbase = W2 + (size_t)e * DH * DOUT + n0 + wn;

    int ty = tid >> 4;
    int tx = tid & 15;

    float acc[4][4];
#pragma unroll
    for (int i = 0; i < 4; i++)
#pragma unroll
        for (int j = 0; j < 4; j++) acc[i][j] = 0.f;

    for (int k0 = 0; k0 < DH; k0 += BK) {
        float4 hv = *(const float4*)(hrow + k0 + lk);
        Hs[lk + 0][lm] = hv.x;
        Hs[lk + 1][lm] = hv.y;
        Hs[lk + 2][lm] = hv.z;
        Hs[lk + 3][lm] = hv.w;
        *(float4*)&Ws[wk][wn] = *(const float4*)(wbase + (size_t)(k0 + wk) * DOUT);
        __syncthreads();
#pragma unroll
        for (int k = 0; k < BK; k++) {
            float4 a = *(float4*)&Hs[k][ty * 4];
            float4 b = *(float4*)&Ws[k][tx * 4];
            acc[0][0] += a.x * b.x; acc[0][1] += a.x * b.y; acc[0][2] += a.x * b.z; acc[0][3] += a.x * b.w;
            acc[1][0] += a.y * b.x; acc[1][1] += a.y * b.y; acc[1][2] += a.y * b.z; acc[1][3] += a.y * b.w;
            acc[2][0] += a.z * b.x; acc[2][1] += a.z * b.y; acc[2][2] += a.z * b.z; acc[2][3] += a.z * b.w;
            acc[3][0] += a.w * b.x; acc[3][1] += a.w * b.y; acc[3][2] += a.w * b.z; acc[3][3] += a.w * b.w;
        }
        __syncthreads();
    }

    float4 bb = *(const float4*)(b2 + (size_t)e * DOUT + n0 + tx * 4);
#pragma unroll
    for (int i = 0; i < 4; i++) {
        int row = m0 + ty * 4 + i;
        if (row < M) {
            int   tok = g_tok[e * NTOK + row];
            float w   = g_wt[e * NTOK + row];
            float* o  = out + (size_t)tok * DOUT + n0 + tx * 4;
            atomicAdd(o + 0, w * (acc[i][0] + bb.x));
            atomicAdd(o + 1, w * (acc[i][1] + bb.y));
            atomicAdd(o + 2, w * (acc[i][2] + bb.z));
            atomicAdd(o + 3, w * (acc[i][3] + bb.w));
        }
    }
}

// ---------------------------------------------------------------------------
// Launch
// ---------------------------------------------------------------------------
extern "C" void kernel_launch(void* const* d_in, const int* in_sizes, int n_in,
                              void* d_out, int out_size) {
    const float* x  = (const float*)d_in[0];
    const float* Wg = (const float*)d_in[1];
    const float* bg = (const float*)d_in[2];
    const float* W1 = (const float*)d_in[3];
    const float* b1 = (const float*)d_in[4];
    const float* W2 = (const float*)d_in[5];
    const float* b2 = (const float*)d_in[6];

    int N = in_sizes[0] / DIN;   // 16384
    float* out      = (float*)d_out;                    // [N, 1024]
    float* gate_out = (float*)d_out + (size_t)N * DOUT; // [N, 8]

    // 0) zero out-region + counters
    int n4 = (N * DOUT) / 4;
    moe_zero_kernel<<<2048, 256>>>((float4*)out, n4);

    // 1) gating
    int gate_blocks = (N * 32 + 255) / 256;
    moe_gate_kernel<<<gate_blocks, 256>>>(x, Wg, bg, gate_out, N);

    // 2) expert GEMM1: H = relu(X @ W1 + b1)
    dim3 g1(DH / BN, (N + BM - 1) / BM, NEXP);
    moe_gemm1_kernel<<<g1, 256>>>(x, W1, b1);

    // 3) expert GEMM2 + combine
    dim3 g2(DOUT / BN, (N + BM - 1) / BM, NEXP);
    moe_gemm2_kernel<<<g2, 256>>>(W2, b2, out);
}

// round 2
// speedup vs baseline: 1.0032x; 1.0032x over previous
#include <cuda_runtime.h>

#define NTOK 16384
#define DIN  1024
#define DH   256
#define DOUT 1024
#define NEXP 8

// scratch (static device globals; no allocation at runtime)
__device__ int   g_count[NEXP];
__device__ int   g_tok[NEXP * NTOK];
__device__ float g_wt[NEXP * NTOK];
__device__ float g_H[(size_t)NEXP * NTOK * DH];   // 128 MiB

// ---------------------------------------------------------------------------
// Kernel 0: zero the accumulated output region + expert counters
// ---------------------------------------------------------------------------
__global__ void moe_zero_kernel(float4* __restrict__ out4, int n4) {
    int i = blockIdx.x * blockDim.x + threadIdx.x;
    if (i < NEXP) g_count[i] = 0;
    float4 z = make_float4(0.f, 0.f, 0.f, 0.f);
    for (int idx = i; idx < n4; idx += gridDim.x * blockDim.x) out4[idx] = z;
}

// ---------------------------------------------------------------------------
// Kernel 1: gating. One warp per token: 8 fp32 dot products (exact), top-2,
// softmax, scatter into per-expert lists.
// ---------------------------------------------------------------------------
__global__ void moe_gate_kernel(const float* __restrict__ x,
                                const float* __restrict__ Wg,
                                const float* __restrict__ bg,
                                float* __restrict__ gate_out,  // [N, 8]
                                int N) {
    int warp = (blockIdx.x * blockDim.x + threadIdx.x) >> 5;
    int lane = threadIdx.x & 31;
    if (warp >= N) return;

    const float* xr = x + (size_t)warp * DIN;
    float acc[8];
#pragma unroll
    for (int e = 0; e < 8; e++) acc[e] = 0.f;

    for (int k = lane; k < DIN; k += 32) {
        float xv = xr[k];
        const float4* wrow = (const float4*)(Wg + (size_t)k * 8);
        float4 w0 = wrow[0];
        float4 w1 = wrow[1];
        acc[0] += xv * w0.x; acc[1] += xv * w0.y;
        acc[2] += xv * w0.z; acc[3] += xv * w0.w;
        acc[4] += xv * w1.x; acc[5] += xv * w1.y;
        acc[6] += xv * w1.z; acc[7] += xv * w1.w;
    }
#pragma unroll
    for (int off = 16; off; off >>= 1) {
#pragma unroll
        for (int e = 0; e < 8; e++)
            acc[e] += __shfl_xor_sync(0xFFFFFFFFu, acc[e], off);
    }

    if (lane == 0) {
        float lg[8];
#pragma unroll
        for (int e = 0; e < 8; e++) {
            lg[e] = acc[e] + bg[e];
            gate_out[(size_t)warp * 8 + e] = lg[e];
        }
        // top-2 (first index wins ties, matching jax top_k)
        int i0 = 0; float m0 = lg[0];
#pragma unroll
        for (int e = 1; e < 8; e++) if (lg[e] > m0) { m0 = lg[e]; i0 = e; }
        int i1 = -1; float m1 = -1e30f;
#pragma unroll
        for (int e = 0; e < 8; e++) if (e != i0 && lg[e] > m1) { m1 = lg[e]; i1 = e; }
        float e1 = __expf(m1 - m0);
        float inv = 1.f / (1.f + e1);
        float w0 = inv;
        float w1 = e1 * inv;

        int p0 = atomicAdd(&g_count[i0], 1);
        g_tok[i0 * NTOK + p0] = warp;
        g_wt[i0 * NTOK + p0] = w0;
        int p1 = atomicAdd(&g_count[i1], 1);
        g_tok[i1 * NTOK + p1] = warp;
        g_wt[i1 * NTOK + p1] = w1;
    }
}

// ---------------------------------------------------------------------------
// Tiled fp32 GEMM params
// ---------------------------------------------------------------------------
#define BM 64
#define BN 64
#define BK 16

// Kernel 2: H = relu(X[gathered] @ W1[e] + b1[e])     (K = 1024, N-dim = 256)
__global__ void __launch_bounds__(256, 4)
moe_gemm1_kernel(const float* __restrict__ x,
                 const float* __restrict__ W1,
                 const float* __restrict__ b1) {
    int e  = blockIdx.z;
    int m0 = blockIdx.y * BM;
    int n0 = blockIdx.x * BN;
    int M  = g_count[e];
    if (m0 >= M) return;

    __shared__ float Xs[BK][BM];
    __shared__ float Ws[BK][BN];

    int tid = threadIdx.x;
    // X loads: thread -> (m, k-offset)
    int lm = tid >> 2;
    int lk = (tid & 3) * 4;
    int gm = m0 + lm;
    const float* xrow = (gm < M) ? (x + (size_t)g_tok[e * NTOK + gm] * DIN) : nullptr;
    // W loads: thread -> (k, n-offset)
    int wk = tid >> 4;
    int wn = (tid & 15) * 4;
    const float* wbase = W1 + (size_t)e * DIN * DH + n0 + wn;

    int ty = tid >> 4;   // 0..15 -> m group
    int tx = tid & 15;   // 0..15 -> n group

    float acc[4][4];
#pragma unroll
    for (int i = 0; i < 4; i++)
#pragma unroll
        for (int j = 0; j < 4; j++) acc[i][j] = 0.f;

    for (int k0 = 0; k0 < DIN; k0 += BK) {
        float4 xv = xrow ? *(const float4*)(xrow + k0 + lk)
                         : make_float4(0.f, 0.f, 0.f, 0.f);
        Xs[lk + 0][lm] = xv.x;
        Xs[lk + 1][lm] = xv.y;
        Xs[lk + 2][lm] = xv.z;
        Xs[lk + 3][lm] = xv.w;
        *(float4*)&Ws[wk][wn] = *(const float4*)(wbase + (size_t)(k0 + wk) * DH);
        __syncthreads();
#pragma unroll
        for (int k = 0; k < BK; k++) {
            float4 a = *(float4*)&Xs[k][ty * 4];
            float4 b = *(float4*)&Ws[k][tx * 4];
            acc[0][0] += a.x * b.x; acc[0][1] += a.x * b.y; acc[0][2] += a.x * b.z; acc[0][3] += a.x * b.w;
            acc[1][0] += a.y * b.x; acc[1][1] += a.y * b.y; acc[1][2] += a.y * b.z; acc[1][3] += a.y * b.w;
            acc[2][0] += a.z * b.x; acc[2][1] += a.z * b.y; acc[2][2] += a.z * b.z; acc[2][3] += a.z * b.w;
            acc[3][0] += a.w * b.x; acc[3][1] += a.w * b.y; acc[3][2] += a.w * b.z; acc[3][3] += a.w * b.w;
        }
        __syncthreads();
    }

    float4 bb = *(const float4*)(b1 + (size_t)e * DH + n0 + tx * 4);
#pragma unroll
    for (int i = 0; i < 4; i++) {
        int row = m0 + ty * 4 + i;
        if (row < M) {
            float4 h;
            h.x = fmaxf(acc[i][0] + bb.x, 0.f);
            h.y = fmaxf(acc[i][1] + bb.y, 0.f);
            h.z = fmaxf(acc[i][2] + bb.z, 0.f);
            h.w = fmaxf(acc[i][3] + bb.w, 0.f);
            *(float4*)(g_H + ((size_t)e * NTOK + row) * DH + n0 + tx * 4) = h;
        }
    }
}

// Kernel 3: Y = H @ W2[e] + b2[e]; out[tok] += w * Y  (K = 256, N-dim = 1024)
__global__ void __launch_bounds__(256, 4)
moe_gemm2_kernel(const float* __restrict__ W2,
                 const float* __restrict__ b2,
                 float* __restrict__ out) {
    int e  = blockIdx.z;
    int m0 = blockIdx.y * BM;
    int n0 = blockIdx.x * BN;
    int M  = g_count[e];
    if (m0 >= M) return;

    __shared__ float Hs[BK][BM];
    __shared__ float Ws[BK][BN];

    int tid = threadIdx.x;
    int lm = tid >> 2;
    int lk = (tid & 3) * 4;
    const float* hrow = g_H + ((size_t)e * NTOK + (m0 + lm)) * DH;   // always in-bounds capacity
    int wk = tid >> 4;
    int wn = (tid & 15) * 4;
    const float* wbase = W2 + (size_t)e * DH * DOUT + n0 + wn;

    int ty = tid >> 4;
    int tx = tid & 15;

    float acc[4][4];
#pragma unroll
    for (int i = 0; i < 4; i++)
#pragma unroll
        for (int j = 0; j < 4; j++) acc[i][j] = 0.f;

    for (int k0 = 0; k0 < DH; k0 += BK) {
        float4 hv = *(const float4*)(hrow + k0 + lk);
        Hs[lk + 0][lm] = hv.x;
        Hs[lk + 1][lm] = hv.y;
        Hs[lk + 2][lm] = hv.z;
        Hs[lk + 3][lm] = hv.w;
        *(float4*)&Ws[wk][wn] = *(const float4*)(wbase + (size_t)(k0 + wk) * DOUT);
        __syncthreads();
#pragma unroll
        for (int k = 0; k < BK; k++) {
            float4 a = *(float4*)&Hs[k][ty * 4];
            float4 b = *(float4*)&Ws[k][tx * 4];
            acc[0][0] += a.x * b.x; acc[0][1] += a.x * b.y; acc[0][2] += a.x * b.z; acc[0][3] += a.x * b.w;
            acc[1][0] += a.y * b.x; acc[1][1] += a.y * b.y; acc[1][2] += a.y * b.z; acc[1][3] += a.y * b.w;
            acc[2][0] += a.z * b.x; acc[2][1] += a.z * b.y; acc[2][2] += a.z * b.z; acc[2][3] += a.z * b.w;
            acc[3][0] += a.w * b.x; acc[3][1] += a.w * b.y; acc[3][2] += a.w * b.z; acc[3][3] += a.w * b.w;
        }
        __syncthreads();
    }

    float4 bb = *(const float4*)(b2 + (size_t)e * DOUT + n0 + tx * 4);
#pragma unroll
    for (int i = 0; i < 4; i++) {
        int row = m0 + ty * 4 + i;
        if (row < M) {
            int   tok = g_tok[e * NTOK + row];
            float w   = g_wt[e * NTOK + row];
            float* o  = out + (size_t)tok * DOUT + n0 + tx * 4;
            atomicAdd(o + 0, w * (acc[i][0] + bb.x));
            atomicAdd(o + 1, w * (acc[i][1] + bb.y));
            atomicAdd(o + 2, w * (acc[i][2] + bb.z));
            atomicAdd(o + 3, w * (acc[i][3] + bb.w));
        }
    }
}

// ---------------------------------------------------------------------------
// Launch
// ---------------------------------------------------------------------------
extern "C" void kernel_launch(void* const* d_in, const int* in_sizes, int n_in,
                              void* d_out, int out_size) {
    const float* x  = (const float*)d_in[0];
    const float* Wg = (const float*)d_in[1];
    const float* bg = (const float*)d_in[2];
    const float* W1 = (const float*)d_in[3];
    const float* b1 = (const float*)d_in[4];
    const float* W2 = (const float*)d_in[5];
    const float* b2 = (const float*)d_in[6];

    int N = in_sizes[0] / DIN;   // 16384
    float* out      = (float*)d_out;                    // [N, 1024]
    float* gate_out = (float*)d_out + (size_t)N * DOUT; // [N, 8]

    // 0) zero out-region + counters
    int n4 = (N * DOUT) / 4;
    moe_zero_kernel<<<2048, 256>>>((float4*)out, n4);

    // 1) gating
    int gate_blocks = (N * 32 + 255) / 256;
    moe_gate_kernel<<<gate_blocks, 256>>>(x, Wg, bg, gate_out, N);

    // 2) expert GEMM1: H = relu(X @ W1 + b1)
    dim3 g1(DH / BN, (N + BM - 1) / BM, NEXP);
    moe_gemm1_kernel<<<g1, 256>>>(x, W1, b1);

    // 3) expert GEMM2 + combine
    dim3 g2(DOUT / BN, (N + BM - 1) / BM, NEXP);
    moe_gemm2_kernel<<<g2, 256>>>(W2, b2, out);
}

// round 3
// speedup vs baseline: 1.0035x; 1.0002x over previous
#include <cuda_runtime.h>

#define NTOK 16384
#define DIN  1024
#define DH   256
#define DOUT 1024
#define NEXP 8

// scratch (static device globals; no allocation at runtime)
__device__ int   g_count[NEXP];
__device__ int   g_tok[NEXP * NTOK];
__device__ float g_wt[NEXP * NTOK];
__device__ float g_H[(size_t)NEXP * NTOK * DH];   // 128 MiB

// ---------------------------------------------------------------------------
// Kernel 0: zero the accumulated output region + expert counters
// ---------------------------------------------------------------------------
__global__ void moe_zero_kernel(float4* __restrict__ out4, int n4) {
    int i = blockIdx.x * blockDim.x + threadIdx.x;
    if (i < NEXP) g_count[i] = 0;
    float4 z = make_float4(0.f, 0.f, 0.f, 0.f);
    for (int idx = i; idx < n4; idx += gridDim.x * blockDim.x) out4[idx] = z;
}

// ---------------------------------------------------------------------------
// Kernel 1: gating. One warp per token: 8 fp32 dot products (exact), top-2,
// softmax, scatter into per-expert lists.
// ---------------------------------------------------------------------------
__global__ void moe_gate_kernel(const float* __restrict__ x,
                                const float* __restrict__ Wg,
                                const float* __restrict__ bg,
                                float* __restrict__ gate_out,  // [N, 8]
                                int N) {
    int warp = (blockIdx.x * blockDim.x + threadIdx.x) >> 5;
    int lane = threadIdx.x & 31;
    if (warp >= N) return;

    const float* xr = x + (size_t)warp * DIN;
    float acc[8];
#pragma unroll
    for (int e = 0; e < 8; e++) acc[e] = 0.f;

    for (int k = lane; k < DIN; k += 32) {
        float xv = xr[k];
        const float4* wrow = (const float4*)(Wg + (size_t)k * 8);
        float4 w0 = wrow[0];
        float4 w1 = wrow[1];
        acc[0] += xv * w0.x; acc[1] += xv * w0.y;
        acc[2] += xv * w0.z; acc[3] += xv * w0.w;
        acc[4] += xv * w1.x; acc[5] += xv * w1.y;
        acc[6] += xv * w1.z; acc[7] += xv * w1.w;
    }
#pragma unroll
    for (int off = 16; off; off >>= 1) {
#pragma unroll
        for (int e = 0; e < 8; e++)
            acc[e] += __shfl_xor_sync(0xFFFFFFFFu, acc[e], off);
    }

    if (lane == 0) {
        float lg[8];
#pragma unroll
        for (int e = 0; e < 8; e++) {
            lg[e] = acc[e] + bg[e];
            gate_out[(size_t)warp * 8 + e] = lg[e];
        }
        // top-2 (first index wins ties, matching jax top_k)
        int i0 = 0; float m0 = lg[0];
#pragma unroll
        for (int e = 1; e < 8; e++) if (lg[e] > m0) { m0 = lg[e]; i0 = e; }
        int i1 = -1; float m1 = -1e30f;
#pragma unroll
        for (int e = 0; e < 8; e++) if (e != i0 && lg[e] > m1) { m1 = lg[e]; i1 = e; }
        float e1 = __expf(m1 - m0);
        float inv = 1.f / (1.f + e1);
        float w0 = inv;
        float w1 = e1 * inv;

        int p0 = atomicAdd(&g_count[i0], 1);
        g_tok[i0 * NTOK + p0] = warp;
        g_wt[i0 * NTOK + p0] = w0;
        int p1 = atomicAdd(&g_count[i1], 1);
        g_tok[i1 * NTOK + p1] = warp;
        g_wt[i1 * NTOK + p1] = w1;
    }
}

// ---------------------------------------------------------------------------
// Tiled fp32 GEMM params
// ---------------------------------------------------------------------------
#define BM 64
#define BN 64
#define BK 16

// Kernel 2: H = relu(X[gathered] @ W1[e] + b1[e])     (K = 1024, N-dim = 256)
__global__ void __launch_bounds__(256, 4)
moe_gemm1_kernel(const float* __restrict__ x,
                 const float* __restrict__ W1,
                 const float* __restrict__ b1) {
    int e  = blockIdx.z;
    int m0 = blockIdx.y * BM;
    int n0 = blockIdx.x * BN;
    int M  = g_count[e];
    if (m0 >= M) return;

    __shared__ float Xs[BK][BM];
    __shared__ float Ws[BK][BN];

    int tid = threadIdx.x;
    // X loads: thread -> (m, k-offset)
    int lm = tid >> 2;
    int lk = (tid & 3) * 4;
    int gm = m0 + lm;
    const float* xrow = (gm < M) ? (x + (size_t)g_tok[e * NTOK + gm] * DIN) : nullptr;
    // W loads: thread -> (k, n-offset)
    int wk = tid >> 4;
    int wn = (tid & 15) * 4;
    const float* wbase = W1 + (size_t)e * DIN * DH + n0 + wn;

    int ty = tid >> 4;   // 0..15 -> m group
    int tx = tid & 15;   // 0..15 -> n group

    float acc[4][4];
#pragma unroll
    for (int i = 0; i < 4; i++)
#pragma unroll
        for (int j = 0; j < 4; j++) acc[i][j] = 0.f;

    for (int k0 = 0; k0 < DIN; k0 += BK) {
        float4 xv = xrow ? *(const float4*)(xrow + k0 + lk)
                         : make_float4(0.f, 0.f, 0.f, 0.f);
        Xs[lk + 0][lm] = xv.x;
        Xs[lk + 1][lm] = xv.y;
        Xs[lk + 2][lm] = xv.z;
        Xs[lk + 3][lm] = xv.w;
        *(float4*)&Ws[wk][wn] = *(const float4*)(wbase + (size_t)(k0 + wk) * DH);
        __syncthreads();
#pragma unroll
        for (int k = 0; k < BK; k++) {
            float4 a = *(float4*)&Xs[k][ty * 4];
            float4 b = *(float4*)&Ws[k][tx * 4];
            acc[0][0] += a.x * b.x; acc[0][1] += a.x * b.y; acc[0][2] += a.x * b.z; acc[0][3] += a.x * b.w;
            acc[1][0] += a.y * b.x; acc[1][1] += a.y * b.y; acc[1][2] += a.y * b.z; acc[1][3] += a.y * b.w;
            acc[2][0] += a.z * b.x; acc[2][1] += a.z * b.y; acc[2][2] += a.z * b.z; acc[2][3] += a.z * b.w;
            acc[3][0] += a.w * b.x; acc[3][1] += a.w * b.y; acc[3][2] += a.w * b.z; acc[3][3] += a.w * b.w;
        }
        __syncthreads();
    }

    float4 bb = *(const float4*)(b1 + (size_t)e * DH + n0 + tx * 4);
#pragma unroll
    for (int i = 0; i < 4; i++) {
        int row = m0 + ty * 4 + i;
        if (row < M) {
            float4 h;
            h.x = fmaxf(acc[i][0] + bb.x, 0.f);
            h.y = fmaxf(acc[i][1] + bb.y, 0.f);
            h.z = fmaxf(acc[i][2] + bb.z, 0.f);
            h.w = fmaxf(acc[i][3] + bb.w, 0.f);
            *(float4*)(g_H + ((size_t)e * NTOK + row) * DH + n0 + tx * 4) = h;
        }
    }
}

// Kernel 3: Y = H @ W2[e] + b2[e]; out[tok] += w * Y  (K = 256, N-dim = 1024)
__global__ void __launch_bounds__(256, 4)
moe_gemm2_kernel(const float* __restrict__ W2,
                 const float* __restrict__ b2,
                 float* __restrict__ out) {
    int e  = blockIdx.z;
    int m0 = blockIdx.y * BM;
    int n0 = blockIdx.x * BN;
    int M  = g_count[e];
    if (m0 >= M) return;

    __shared__ float Hs[BK][BM];
    __shared__ float Ws[BK][BN];

    int tid = threadIdx.x;
    int lm = tid >> 2;
    int lk = (tid & 3) * 4;
    const float* hrow = g_H + ((size_t)e * NTOK + (m0 + lm)) * DH;   // always in-bounds capacity
    int wk = tid >> 4;
    int wn = (tid & 15) * 4;
    const float* wbase = W2 + (size_t)e * DH * DOUT + n0 + wn;

    int ty = tid >> 4;
    int tx = tid & 15;

    float acc[4][4];
#pragma unroll
    for (int i = 0; i < 4; i++)
#pragma unroll
        for (int j = 0; j < 4; j++) acc[i][j] = 0.f;

    for (int k0 = 0; k0 < DH; k0 += BK) {
        float4 hv = *(const float4*)(hrow + k0 + lk);
        Hs[lk + 0][lm] = hv.x;
        Hs[lk + 1][lm] = hv.y;
        Hs[lk + 2][lm] = hv.z;
        Hs[lk + 3][lm] = hv.w;
        *(float4*)&Ws[wk][wn] = *(const float4*)(wbase + (size_t)(k0 + wk) * DOUT);
        __syncthreads();
#pragma unroll
        for (int k = 0; k < BK; k++) {
            float4 a = *(float4*)&Hs[k][ty * 4];
            float4 b = *(float4*)&Ws[k][tx * 4];
            acc[0][0] += a.x * b.x; acc[0][1] += a.x * b.y; acc[0][2] += a.x * b.z; acc[0][3] += a.x * b.w;
            acc[1][0] += a.y * b.x; acc[1][1] += a.y * b.y; acc[1][2] += a.y * b.z; acc[1][3] += a.y * b.w;
            acc[2][0] += a.z * b.x; acc[2][1] += a.z * b.y; acc[2][2] += a.z * b.z; acc[2][3] += a.z * b.w;
            acc[3][0] += a.w * b.x; acc[3][1] += a.w * b.y; acc[3][2] += a.w * b.z; acc[3][3] += a.w * b.w;
        }
        __syncthreads();
    }

    float4 bb = *(const float4*)(b2 + (size_t)e * DOUT + n0 + tx * 4);
#pragma unroll
    for (int i = 0; i < 4; i++) {
        int row = m0 + ty * 4 + i;
        if (row < M) {
            int   tok = g_tok[e * NTOK + row];
            float w   = g_wt[e * NTOK + row];
            float* o  = out + (size_t)tok * DOUT + n0 + tx * 4;
            atomicAdd(o + 0, w * (acc[i][0] + bb.x));
            atomicAdd(o + 1, w * (acc[i][1] + bb.y));
            atomicAdd(o + 2, w * (acc[i][2] + bb.z));
            atomicAdd(o + 3, w * (acc[i][3] + bb.w));
        }
    }
}

// ---------------------------------------------------------------------------
// Launch
// ---------------------------------------------------------------------------
extern "C" void kernel_launch(void* const* d_in, const int* in_sizes, int n_in,
                              void* d_out, int out_size) {
    const float* x  = (const float*)d_in[0];
    const float* Wg = (const float*)d_in[1];
    const float* bg = (const float*)d_in[2];
    const float* W1 = (const float*)d_in[3];
    const float* b1 = (const float*)d_in[4];
    const float* W2 = (const float*)d_in[5];
    const float* b2 = (const float*)d_in[6];

    int N = in_sizes[0] / DIN;   // 16384
    float* out      = (float*)d_out;                    // [N, 1024]
    float* gate_out = (float*)d_out + (size_t)N * DOUT; // [N, 8]

    // 0) zero out-region + counters
    int n4 = (N * DOUT) / 4;
    moe_zero_kernel<<<2048, 256>>>((float4*)out, n4);

    // 1) gating
    int gate_blocks = (N * 32 + 255) / 256;
    moe_gate_kernel<<<gate_blocks, 256>>>(x, Wg, bg, gate_out, N);

    // 2) expert GEMM1: H = relu(X @ W1 + b1)
    dim3 g1(DH / BN, (N + BM - 1) / BM, NEXP);
    moe_gemm1_kernel<<<g1, 256>>>(x, W1, b1);

    // 3) expert GEMM2 + combine
    dim3 g2(DOUT / BN, (N + BM - 1) / BM, NEXP);
    moe_gemm2_kernel<<<g2, 256>>>(W2, b2, out);
}

// round 4
// speedup vs baseline: 2.0722x; 2.0650x over previous
#include <cuda_runtime.h>
#include <cstdint>

#define NTOK 16384
#define DIN  1024
#define DH   256
#define DOUT 1024
#define NEXP 8

// scratch (static device globals; no allocation at runtime)
__device__ int   g_count[NEXP];
__device__ int   g_tok[NEXP * NTOK];
__device__ float g_wt[NEXP * NTOK];
__device__ float g_H[(size_t)NEXP * NTOK * DH];   // 128 MiB

// ---------------------------------------------------------------------------
// Kernel 0: zero the accumulated output region + expert counters
// ---------------------------------------------------------------------------
__global__ void moe_zero_kernel(float4* __restrict__ out4, int n4) {
    int i = blockIdx.x * blockDim.x + threadIdx.x;
    if (i < NEXP) g_count[i] = 0;
    float4 z = make_float4(0.f, 0.f, 0.f, 0.f);
    for (int idx = i; idx < n4; idx += gridDim.x * blockDim.x) out4[idx] = z;
}

// ---------------------------------------------------------------------------
// Kernel 1: gating. One warp per token: 8 fp32 dot products (exact), top-2,
// softmax, scatter into per-expert lists.
// ---------------------------------------------------------------------------
__global__ void moe_gate_kernel(const float* __restrict__ x,
                                const float* __restrict__ Wg,
                                const float* __restrict__ bg,
                                float* __restrict__ gate_out,  // [N, 8]
                                int N) {
    int warp = (blockIdx.x * blockDim.x + threadIdx.x) >> 5;
    int lane = threadIdx.x & 31;
    if (warp >= N) return;

    const float* xr = x + (size_t)warp * DIN;
    float acc[8];
#pragma unroll
    for (int e = 0; e < 8; e++) acc[e] = 0.f;

    for (int k = lane; k < DIN; k += 32) {
        float xv = xr[k];
        const float4* wrow = (const float4*)(Wg + (size_t)k * 8);
        float4 w0 = wrow[0];
        float4 w1 = wrow[1];
        acc[0] += xv * w0.x; acc[1] += xv * w0.y;
        acc[2] += xv * w0.z; acc[3] += xv * w0.w;
        acc[4] += xv * w1.x; acc[5] += xv * w1.y;
        acc[6] += xv * w1.z; acc[7] += xv * w1.w;
    }
#pragma unroll
    for (int off = 16; off; off >>= 1) {
#pragma unroll
        for (int e = 0; e < 8; e++)
            acc[e] += __shfl_xor_sync(0xFFFFFFFFu, acc[e], off);
    }

    if (lane == 0) {
        float lg[8];
#pragma unroll
        for (int e = 0; e < 8; e++) {
            lg[e] = acc[e] + bg[e];
            gate_out[(size_t)warp * 8 + e] = lg[e];
        }
        int i0 = 0; float m0 = lg[0];
#pragma unroll
        for (int e = 1; e < 8; e++) if (lg[e] > m0) { m0 = lg[e]; i0 = e; }
        int i1 = -1; float m1 = -1e30f;
#pragma unroll
        for (int e = 0; e < 8; e++) if (e != i0 && lg[e] > m1) { m1 = lg[e]; i1 = e; }
        float e1 = __expf(m1 - m0);
        float inv = 1.f / (1.f + e1);
        float w0 = inv;
        float w1 = e1 * inv;

        int p0 = atomicAdd(&g_count[i0], 1);
        g_tok[i0 * NTOK + p0] = warp;
        g_wt[i0 * NTOK + p0] = w0;
        int p1 = atomicAdd(&g_count[i1], 1);
        g_tok[i1 * NTOK + p1] = warp;
        g_wt[i1 * NTOK + p1] = w1;
    }
}

// ---------------------------------------------------------------------------
// TF32 mma helpers
// ---------------------------------------------------------------------------
__device__ __forceinline__ uint32_t f32_to_tf32(float f) {
    uint32_t r;
    asm("cvt.rna.tf32.f32 %0, %1;" : "=r"(r) : "f"(f));
    return r;
}

__device__ __forceinline__ void mma_tf32(float* c, const uint32_t* a, const uint32_t* b) {
    asm volatile(
        "mma.sync.aligned.m16n8k8.row.col.f32.tf32.tf32.f32 "
        "{%0,%1,%2,%3}, {%4,%5,%6,%7}, {%8,%9}, {%0,%1,%2,%3};\n"
        : "+f"(c[0]), "+f"(c[1]), "+f"(c[2]), "+f"(c[3])
        : "r"(a[0]), "r"(a[1]), "r"(a[2]), "r"(a[3]), "r"(b[0]), "r"(b[1]));
}

// Tiling: block 128x64, 8 warps (4 m x 2 n), warp tile 32x32 (2x4 atoms), BK=32
#define BM 128
#define BN 64
#define BK 32
#define A_STRIDE 36   // 36 % 32 == 4 -> conflict-free frag loads
#define B_STRIDE 72   // 72 % 32 == 8 -> conflict-free frag loads

// ---------------------------------------------------------------------------
// Kernel 2: H = relu(X[gathered] @ W1[e] + b1[e])   K=1024, Ncols=256
// ---------------------------------------------------------------------------
__global__ void __launch_bounds__(256, 2)
moe_gemm1_kernel(const float* __restrict__ x,
                 const float* __restrict__ W1,
                 const float* __restrict__ b1) {
    int e  = blockIdx.z;
    int m0 = blockIdx.y * BM;
    int n0 = blockIdx.x * BN;
    int M  = g_count[e];
    if (m0 >= M) return;

    __shared__ uint32_t As[BM][A_STRIDE];
    __shared__ uint32_t Bs[BK][B_STRIDE];

    int tid  = threadIdx.x;
    int wid  = tid >> 5;
    int lane = tid & 31;
    int wm   = wid & 3;          // 0..3 (m)
    int wn   = wid >> 2;         // 0..1 (n)
    int g    = lane >> 2;        // 0..7
    int t    = lane & 3;         // 0..3

    // A staging: row r = tid>>1, 16 floats at col (tid&1)*16
    int ar = tid >> 1;
    int ac = (tid & 1) * 16;
    int gm = m0 + ar;
    bool aval = (gm < M);
    const float* arow = x + (size_t)(aval ? g_tok[e * NTOK + gm] : 0) * DIN + ac;

    // B staging: row rb = tid>>3 (k), 8 floats at col (tid&7)*8
    int brk = tid >> 3;
    int bc  = (tid & 7) * 8;
    const float* bbase = W1 + (size_t)e * DIN * DH + n0 + bc;

    float acc[2][4][4];
#pragma unroll
    for (int i = 0; i < 2; i++)
#pragma unroll
        for (int j = 0; j < 4; j++)
#pragma unroll
            for (int q = 0; q < 4; q++) acc[i][j][q] = 0.f;

    float4 av[4], bv[2];
    // preload chunk 0
#pragma unroll
    for (int q = 0; q < 4; q++)
        av[q] = aval ? *(const float4*)(arow + q * 4) : make_float4(0.f, 0.f, 0.f, 0.f);
    bv[0] = *(const float4*)(bbase + (size_t)brk * DH);
    bv[1] = *(const float4*)(bbase + (size_t)brk * DH + 4);

    const int NK = DIN / BK;     // 32
    for (int kc = 0; kc < NK; kc++) {
        // store staged regs to smem (cvt to tf32)
#pragma unroll
        for (int q = 0; q < 4; q++) {
            As[ar][ac + q * 4 + 0] = f32_to_tf32(av[q].x);
            As[ar][ac + q * 4 + 1] = f32_to_tf32(av[q].y);
            As[ar][ac + q * 4 + 2] = f32_to_tf32(av[q].z);
            As[ar][ac + q * 4 + 3] = f32_to_tf32(av[q].w);
        }
        Bs[brk][bc + 0] = f32_to_tf32(bv[0].x);
        Bs[brk][bc + 1] = f32_to_tf32(bv[0].y);
        Bs[brk][bc + 2] = f32_to_tf32(bv[0].z);
        Bs[brk][bc + 3] = f32_to_tf32(bv[0].w);
        Bs[brk][bc + 4] = f32_to_tf32(bv[1].x);
        Bs[brk][bc + 5] = f32_to_tf32(bv[1].y);
        Bs[brk][bc + 6] = f32_to_tf32(bv[1].z);
        Bs[brk][bc + 7] = f32_to_tf32(bv[1].w);
        __syncthreads();

        // prefetch next chunk
        if (kc + 1 < NK) {
            int k0 = (kc + 1) * BK;
#pragma unroll
            for (int q = 0; q < 4; q++)
                av[q] = aval ? *(const float4*)(arow + k0 + q * 4)
                             : make_float4(0.f, 0.f, 0.f, 0.f);
            bv[0] = *(const float4*)(bbase + (size_t)(k0 + brk) * DH);
            bv[1] = *(const float4*)(bbase + (size_t)(k0 + brk) * DH + 4);
        }

        // compute 4 k-steps
#pragma unroll
        for (int kk = 0; kk < 4; kk++) {
            int kb = kk * 8;
            uint32_t af[2][4], bf[4][2];
#pragma unroll
            for (int i = 0; i < 2; i++) {
                int rb = wm * 32 + i * 16;
                af[i][0] = As[rb + g][kb + t];
                af[i][1] = As[rb + g + 8][kb + t];
                af[i][2] = As[rb + g][kb + t + 4];
                af[i][3] = As[rb + g + 8][kb + t + 4];
            }
#pragma unroll
            for (int j = 0; j < 4; j++) {
                int cb = wn * 32 + j * 8;
                bf[j][0] = Bs[kb + t][cb + g];
                bf[j][1] = Bs[kb + t + 4][cb + g];
            }
#pragma unroll
            for (int i = 0; i < 2; i++)
#pragma unroll
                for (int j = 0; j < 4; j++)
                    mma_tf32(acc[i][j], af[i], bf[j]);
        }
        __syncthreads();
    }

    // epilogue: relu(acc + bias) -> g_H
#pragma unroll
    for (int i = 0; i < 2; i++) {
        int row0 = m0 + wm * 32 + i * 16 + g;
        int row1 = row0 + 8;
#pragma unroll
        for (int j = 0; j < 4; j++) {
            int col = n0 + wn * 32 + j * 8 + 2 * t;
            float bx = b1[(size_t)e * DH + col];
            float by = b1[(size_t)e * DH + col + 1];
            if (row0 < M) {
                float2 h0;
                h0.x = fmaxf(acc[i][j][0] + bx, 0.f);
                h0.y = fmaxf(acc[i][j][1] + by, 0.f);
                *(float2*)(g_H + ((size_t)e * NTOK + row0) * DH + col) = h0;
            }
            if (row1 < M) {
                float2 h1;
                h1.x = fmaxf(acc[i][j][2] + bx, 0.f);
                h1.y = fmaxf(acc[i][j][3] + by, 0.f);
                *(float2*)(g_H + ((size_t)e * NTOK + row1) * DH + col) = h1;
            }
        }
    }
}

// ---------------------------------------------------------------------------
// Kernel 3: Y = H @ W2[e] + b2[e]; out[tok] += w * Y   K=256, Ncols=1024
// ---------------------------------------------------------------------------
__global__ void __launch_bounds__(256, 2)
moe_gemm2_kernel(const float* __restrict__ W2,
                 const float* __restrict__ b2,
                 float* __restrict__ out) {
    int e  = blockIdx.z;
    int m0 = blockIdx.y * BM;
    int n0 = blockIdx.x * BN;
    int M  = g_count[e];
    if (m0 >= M) return;

    __shared__ uint32_t As[BM][A_STRIDE];
    __shared__ uint32_t Bs[BK][B_STRIDE];

    int tid  = threadIdx.x;
    int wid  = tid >> 5;
    int lane = tid & 31;
    int wm   = wid & 3;
    int wn   = wid >> 2;
    int g    = lane >> 2;
    int t    = lane & 3;

    int ar = tid >> 1;
    int ac = (tid & 1) * 16;
    const float* arow = g_H + ((size_t)e * NTOK + (m0 + ar)) * DH + ac;

    int brk = tid >> 3;
    int bc  = (tid & 7) * 8;
    const float* bbase = W2 + (size_t)e * DH * DOUT + n0 + bc;

    float acc[2][4][4];
#pragma unroll
    for (int i = 0; i < 2; i++)
#pragma unroll
        for (int j = 0; j < 4; j++)
#pragma unroll
            for (int q = 0; q < 4; q++) acc[i][j][q] = 0.f;

    bool aval = (m0 + ar < M);   // guard against reading stale garbage
    float4 av[4], bv[2];
#pragma unroll
    for (int q = 0; q < 4; q++)
        av[q] = aval ? *(const float4*)(arow + q * 4) : make_float4(0.f, 0.f, 0.f, 0.f);
    bv[0] = *(const float4*)(bbase + (size_t)brk * DOUT);
    bv[1] = *(const float4*)(bbase + (size_t)brk * DOUT + 4);

    const int NK = DH / BK;      // 8
    for (int kc = 0; kc < NK; kc++) {
#pragma unroll
        for (int q = 0; q < 4; q++) {
            As[ar][ac + q * 4 + 0] = f32_to_tf32(av[q].x);
            As[ar][ac + q * 4 + 1] = f32_to_tf32(av[q].y);
            As[ar][ac + q * 4 + 2] = f32_to_tf32(av[q].z);
            As[ar][ac + q * 4 + 3] = f32_to_tf32(av[q].w);
        }
        Bs[brk][bc + 0] = f32_to_tf32(bv[0].x);
        Bs[brk][bc + 1] = f32_to_tf32(bv[0].y);
        Bs[brk][bc + 2] = f32_to_tf32(bv[0].z);
        Bs[brk][bc + 3] = f32_to_tf32(bv[0].w);
        Bs[brk][bc + 4] = f32_to_tf32(bv[1].x);
        Bs[brk][bc + 5] = f32_to_tf32(bv[1].y);
        Bs[brk][bc + 6] = f32_to_tf32(bv[1].z);
        Bs[brk][bc + 7] = f32_to_tf32(bv[1].w);
        __syncthreads();

        if (kc + 1 < NK) {
            int k0 = (kc + 1) * BK;
#pragma unroll
            for (int q = 0; q < 4; q++)
                av[q] = aval ? *(const float4*)(arow + k0 + q * 4)
                             : make_float4(0.f, 0.f, 0.f, 0.f);
            bv[0] = *(const float4*)(bbase + (size_t)(k0 + brk) * DOUT);
            bv[1] = *(const float4*)(bbase + (size_t)(k0 + brk) * DOUT + 4);
        }

#pragma unroll
        for (int kk = 0; kk < 4; kk++) {
            int kb = kk * 8;
            uint32_t af[2][4], bf[4][2];
#pragma unroll
            for (int i = 0; i < 2; i++) {
                int rb = wm * 32 + i * 16;
                af[i][0] = As[rb + g][kb + t];
                af[i][1] = As[rb + g + 8][kb + t];
                af[i][2] = As[rb + g][kb + t + 4];
                af[i][3] = As[rb + g + 8][kb + t + 4];
            }
#pragma unroll
            for (int j = 0; j < 4; j++) {
                int cb = wn * 32 + j * 8;
                bf[j][0] = Bs[kb + t][cb + g];
                bf[j][1] = Bs[kb + t + 4][cb + g];
            }
#pragma unroll
            for (int i = 0; i < 2; i++)
#pragma unroll
                for (int j = 0; j < 4; j++)
                    mma_tf32(acc[i][j], af[i], bf[j]);
        }
        __syncthreads();
    }

    // epilogue: out[tok] += w * (acc + bias)
#pragma unroll
    for (int i = 0; i < 2; i++) {
        int row0 = m0 + wm * 32 + i * 16 + g;
        int row1 = row0 + 8;
        int tok0 = 0, tok1 = 0;
        float w0 = 0.f, w1 = 0.f;
        if (row0 < M) { tok0 = g_tok[e * NTOK + row0]; w0 = g_wt[e * NTOK + row0]; }
        if (row1 < M) { tok1 = g_tok[e * NTOK + row1]; w1 = g_wt[e * NTOK + row1]; }
#pragma unroll
        for (int j = 0; j < 4; j++) {
            int col = n0 + wn * 32 + j * 8 + 2 * t;
            float bx = b2[(size_t)e * DOUT + col];
            float by = b2[(size_t)e * DOUT + col + 1];
            if (row0 < M) {
                float* o = out + (size_t)tok0 * DOUT + col;
                atomicAdd(o + 0, w0 * (acc[i][j][0] + bx));
                atomicAdd(o + 1, w0 * (acc[i][j][1] + by));
            }
            if (row1 < M) {
                float* o = out + (size_t)tok1 * DOUT + col;
                atomicAdd(o + 0, w1 * (acc[i][j][2] + bx));
                atomicAdd(o + 1, w1 * (acc[i][j][3] + by));
            }
        }
    }
}

// ---------------------------------------------------------------------------
// Launch
// ---------------------------------------------------------------------------
extern "C" void kernel_launch(void* const* d_in, const int* in_sizes, int n_in,
                              void* d_out, int out_size) {
    const float* x  = (const float*)d_in[0];
    const float* Wg = (const float*)d_in[1];
    const float* bg = (const float*)d_in[2];
    const float* W1 = (const float*)d_in[3];
    const float* b1 = (const float*)d_in[4];
    const float* W2 = (const float*)d_in[5];
    const float* b2 = (const float*)d_in[6];

    int N = in_sizes[0] / DIN;   // 16384
    float* out      = (float*)d_out;                    // [N, 1024]
    float* gate_out = (float*)d_out + (size_t)N * DOUT; // [N, 8]

    int n4 = (N * DOUT) / 4;
    moe_zero_kernel<<<2048, 256>>>((float4*)out, n4);

    int gate_blocks = (N * 32 + 255) / 256;
    moe_gate_kernel<<<gate_blocks, 256>>>(x, Wg, bg, gate_out, N);

    dim3 g1(DH / BN, (N + BM - 1) / BM, NEXP);     // 4 x 128 x 8
    moe_gemm1_kernel<<<g1, 256>>>(x, W1, b1);

    dim3 g2(DOUT / BN, (N + BM - 1) / BM, NEXP);   // 16 x 128 x 8
    moe_gemm2_kernel<<<g2, 256>>>(W2, b2, out);
}